// round 1
// baseline (speedup 1.0000x reference)
#include <cuda_runtime.h>
#include <math.h>

#define B_ROWS 262144
#define HID 512
#define NB1 512          // blocks for feature-stats kernel
#define RG2 1024         // row-groups for h2 stats

// ---------------- device scratch (static globals: no allocation) ----------------
__device__ float  g_feat[B_ROWS * 4];                 // raw features
__device__ float  g_t1[(size_t)B_ROWS * HID];         // 512 MB: tanh(BN(layer1))
__device__ float  g_h2[(size_t)B_ROWS * HID];         // 512 MB: t1 @ w2
__device__ double g_p1[NB1 * 14];                     // feature sums (4) + moments (10)
__device__ float  g_W1eff[4 * HID];
__device__ float  g_meanX[4];
__device__ float  g_shift1[HID];
__device__ float  g_p2s[RG2 * HID];                   // h2 column partial sums
__device__ float  g_p2q[RG2 * HID];                   // h2 column partial sumsq
__device__ float  g_a2[HID];
__device__ float  g_d2[HID];

__device__ __forceinline__ float ftanh(float x) {
    x = fminf(fmaxf(x, -9.0f), 9.0f);
    float e = __expf(2.0f * x);
    return __fdividef(e - 1.0f, e + 1.0f);
}

// ---------------- K1: features + (sum, second-moment) partials ----------------
__global__ void k1_feat(const float* __restrict__ x,
                        const float* __restrict__ tset,
                        const float* __restrict__ tenv,
                        const float* __restrict__ ctab)
{
    __shared__ float sxs[9], sys[14], stab[9 * 14];
    int tid = threadIdx.x;
    if (tid < 9)   sxs[tid] = tset[tid];
    if (tid < 14)  sys[tid] = tenv[tid];
    if (tid < 126) stab[tid] = ctab[tid];
    __syncthreads();

    double s0 = 0, s1 = 0, s2 = 0, s3 = 0;
    double m00 = 0, m01 = 0, m02 = 0, m03 = 0, m11 = 0, m12 = 0, m13 = 0,
           m22 = 0, m23 = 0, m33 = 0;

    for (int r = blockIdx.x * blockDim.x + tid; r < B_ROWS; r += gridDim.x * blockDim.x) {
        const float* xr = x + (size_t)r * 15;
        float amb = xr[1], fl = xr[2], fr = xr[3];
        float incar = xr[8], breq = xr[9], cin = xr[10];

        // y-axis index (shared between the two interpolations)
        float yq = fminf(fmaxf(amb, sys[0]), sys[13]);
        int j = 0;
        #pragma unroll
        for (int k = 1; k <= 12; k++) j += (sys[k] <= yq);   // == clip(searchsorted-1, 0, ny-2)
        float y0 = sys[j], y1 = sys[j + 1];
        float ty = (yq - y0) / (y1 - y0);

        auto interp = [&](float xq) -> float {
            xq = fminf(fmaxf(xq, sxs[0]), sxs[8]);
            int i = 0;
            #pragma unroll
            for (int k = 1; k <= 7; k++) i += (sxs[k] <= xq);
            float x0 = sxs[i], x1 = sxs[i + 1];
            float tx = (xq - x0) / (x1 - x0);
            float f00 = stab[i * 14 + j],       f01 = stab[i * 14 + j + 1];
            float f10 = stab[(i + 1) * 14 + j], f11 = stab[(i + 1) * 14 + j + 1];
            return f00 * (1.f - tx) * (1.f - ty) + f10 * tx * (1.f - ty)
                 + f01 * (1.f - tx) * ty        + f11 * tx * ty;
        };

        float f0 = interp(fl) - incar;
        float f1 = interp(fr) - incar;
        float f2 = amb;
        float f3 = breq - cin;
        *(float4*)&g_feat[(size_t)r * 4] = make_float4(f0, f1, f2, f3);

        s0 += f0; s1 += f1; s2 += f2; s3 += f3;
        m00 += (double)f0 * f0; m01 += (double)f0 * f1; m02 += (double)f0 * f2; m03 += (double)f0 * f3;
        m11 += (double)f1 * f1; m12 += (double)f1 * f2; m13 += (double)f1 * f3;
        m22 += (double)f2 * f2; m23 += (double)f2 * f3; m33 += (double)f3 * f3;
    }

    __shared__ double red[256];
    double vals[14] = {s0, s1, s2, s3, m00, m01, m02, m03, m11, m12, m13, m22, m23, m33};
    for (int q = 0; q < 14; q++) {
        red[tid] = vals[q];
        __syncthreads();
        for (int off = 128; off > 0; off >>= 1) {
            if (tid < off) red[tid] += red[tid + off];
            __syncthreads();
        }
        if (tid == 0) g_p1[blockIdx.x * 14 + q] = red[0];
        __syncthreads();
    }
}

// ---------------- K2: finalize layer-1 BN fold ----------------
__global__ void k2_fin1(const float* __restrict__ w1,
                        const float* __restrict__ g1,
                        const float* __restrict__ beta1)
{
    __shared__ double acc[14];
    __shared__ float C[4][4];
    int tid = threadIdx.x;
    if (tid < 14) {
        double s = 0;
        for (int p = 0; p < NB1; p++) s += g_p1[p * 14 + tid];
        acc[tid] = s;
    }
    __syncthreads();
    if (tid == 0) {
        double inv = 1.0 / (double)B_ROWS;
        double mm[4];
        for (int a = 0; a < 4; a++) { mm[a] = acc[a] * inv; g_meanX[a] = (float)mm[a]; }
        double M[4][4];
        int idx = 4;
        for (int a = 0; a < 4; a++)
            for (int b = a; b < 4; b++) M[a][b] = acc[idx++] * inv;
        for (int a = 0; a < 4; a++)
            for (int b = a; b < 4; b++) {
                double c = M[a][b] - mm[a] * mm[b];
                C[a][b] = (float)c; C[b][a] = (float)c;
            }
    }
    __syncthreads();
    if (tid < HID) {
        float w[4];
        for (int a = 0; a < 4; a++) w[a] = w1[a * HID + tid];
        float var = 0.f;
        for (int a = 0; a < 4; a++)
            for (int b = 0; b < 4; b++) var += w[a] * C[a][b] * w[b];
        float s = g1[tid] * rsqrtf(var + 1e-5f);
        for (int a = 0; a < 4; a++) g_W1eff[a * HID + tid] = w[a] * s;
        g_shift1[tid] = beta1[tid];
    }
}

// ---------------- K3a: t1 = tanh(Xc @ W1eff + beta1) ----------------
__global__ void k3a_layer1()
{
    int idx = blockIdx.x * blockDim.x + threadIdx.x;   // one thread per (row, 4 cols)
    int r = idx >> 7;
    int jc = (idx & 127) * 4;
    float4 f = *(const float4*)&g_feat[(size_t)r * 4];
    float fc0 = f.x - g_meanX[0], fc1 = f.y - g_meanX[1];
    float fc2 = f.z - g_meanX[2], fc3 = f.w - g_meanX[3];
    float4 o;
    float* ov = &o.x;
    #pragma unroll
    for (int u = 0; u < 4; u++) {
        int j = jc + u;
        float v = fc0 * g_W1eff[0 * HID + j] + fc1 * g_W1eff[1 * HID + j]
                + fc2 * g_W1eff[2 * HID + j] + fc3 * g_W1eff[3 * HID + j]
                + g_shift1[j];
        ov[u] = ftanh(v);
    }
    *(float4*)&g_t1[(size_t)r * HID + jc] = o;
}

// ---------------- K3b: h2 = t1 @ w2  (fp32 SIMT 128x128x16, 8x8/thread) ----------------
#define TM 128
#define TN 128
#define TK 16
__global__ void __launch_bounds__(256, 2) k3b_gemm(const float* __restrict__ w2)
{
    __shared__ float As[TK][TM];   // [k][m]
    __shared__ float Bs[TK][TN];   // [k][n]
    int bm = blockIdx.x;
    int bn = blockIdx.y;
    int tid = threadIdx.x;
    int tx = tid & 15, ty = tid >> 4;          // 16x16 thread grid, 8x8 each

    const float* Aptr = g_t1 + (size_t)bm * TM * HID;
    const float* Bptr = w2 + bn * TN;

    int ar = tid & 63;            // A load: row 0..63 (+64), k4 = (tid>>6)*4
    int ak = (tid >> 6) * 4;
    int br = tid >> 5;            // B load: row 0..7 (+8), col4 = (tid&31)*4
    int bc = (tid & 31) * 4;

    float acc[8][8];
    #pragma unroll
    for (int i = 0; i < 8; i++)
        #pragma unroll
        for (int j = 0; j < 8; j++) acc[i][j] = 0.f;

    for (int kk = 0; kk < HID; kk += TK) {
        #pragma unroll
        for (int h = 0; h < 2; h++) {
            int row = ar + h * 64;
            float4 v = *(const float4*)(Aptr + (size_t)row * HID + kk + ak);
            As[ak + 0][row] = v.x; As[ak + 1][row] = v.y;
            As[ak + 2][row] = v.z; As[ak + 3][row] = v.w;
        }
        #pragma unroll
        for (int h = 0; h < 2; h++) {
            int row = br + h * 8;
            float4 v = *(const float4*)(Bptr + (size_t)(kk + row) * HID + bc);
            *(float4*)&Bs[row][bc] = v;
        }
        __syncthreads();
        #pragma unroll
        for (int k = 0; k < TK; k++) {
            float a[8], b[8];
            *(float4*)&a[0] = *(float4*)&As[k][ty * 8];
            *(float4*)&a[4] = *(float4*)&As[k][ty * 8 + 4];
            *(float4*)&b[0] = *(float4*)&Bs[k][tx * 8];
            *(float4*)&b[4] = *(float4*)&Bs[k][tx * 8 + 4];
            #pragma unroll
            for (int i = 0; i < 8; i++)
                #pragma unroll
                for (int j = 0; j < 8; j++) acc[i][j] += a[i] * b[j];
        }
        __syncthreads();
    }

    float* Cp = g_h2 + (size_t)(bm * TM) * HID + bn * TN;
    #pragma unroll
    for (int i = 0; i < 8; i++) {
        #pragma unroll
        for (int j = 0; j < 8; j += 4) {
            float4 v = make_float4(acc[i][j], acc[i][j + 1], acc[i][j + 2], acc[i][j + 3]);
            *(float4*)(Cp + (size_t)(ty * 8 + i) * HID + tx * 8 + j) = v;
        }
    }
}

// ---------------- K4: per-column partial sums / sumsq of h2 ----------------
__global__ void k4_stats()
{
    int bid = blockIdx.x, t = threadIdx.x;
    size_t base = (size_t)bid * 256 * HID;
    float s0 = 0, q0 = 0, s1 = 0, q1 = 0;
    for (int r = 0; r < 256; r++) {
        const float* row = g_h2 + base + (size_t)r * HID;
        float v0 = row[t], v1 = row[t + 256];
        s0 += v0; q0 += v0 * v0;
        s1 += v1; q1 += v1 * v1;
    }
    g_p2s[bid * HID + t] = s0;       g_p2s[bid * HID + t + 256] = s1;
    g_p2q[bid * HID + t] = q0;       g_p2q[bid * HID + t + 256] = q1;
}

// ---------------- K5: finalize layer-2 BN fold ----------------
__global__ void k5_fin2(const float* __restrict__ g2, const float* __restrict__ beta2)
{
    int c = blockIdx.x * blockDim.x + threadIdx.x;
    if (c >= HID) return;
    double s = 0, q = 0;
    for (int p = 0; p < RG2; p++) { s += g_p2s[p * HID + c]; q += g_p2q[p * HID + c]; }
    double mu  = s / (double)B_ROWS;
    double var = q / (double)B_ROWS - mu * mu;
    float a = g2[c] * rsqrtf((float)var + 1e-5f);
    g_a2[c] = a;
    g_d2[c] = beta2[c] - (float)mu * a;
}

// ---------------- K6: out = tanh(a2*h2 + d2) @ w3 + b3 ----------------
__global__ void k6_out(const float* __restrict__ w3, const float* __restrict__ b3,
                       float* __restrict__ out)
{
    __shared__ float sa[HID], sd[HID], sw[HID];
    int t = threadIdx.x;
    for (int q = t; q < HID; q += 256) { sa[q] = g_a2[q]; sd[q] = g_d2[q]; sw[q] = w3[q]; }
    __syncthreads();
    float bias = b3[0];
    int warp = t >> 5, lane = t & 31;
    int gw = blockIdx.x * 8 + warp;                 // 2048 blocks * 8 warps = 16384
    for (int r = gw; r < B_ROWS; r += 16384) {
        const float* row = g_h2 + (size_t)r * HID;
        float acc = 0.f;
        #pragma unroll
        for (int cc = 0; cc < 16; cc++) {
            int c = cc * 32 + lane;
            acc += ftanh(fmaf(sa[c], row[c], sd[c])) * sw[c];
        }
        #pragma unroll
        for (int off = 16; off; off >>= 1) acc += __shfl_xor_sync(0xffffffffu, acc, off);
        if (lane == 0) out[r] = acc + bias;
    }
}

// ---------------- launch ----------------
extern "C" void kernel_launch(void* const* d_in, const int* in_sizes, int n_in,
                              void* d_out, int out_size)
{
    const float* x     = (const float*)d_in[0];
    const float* tset  = (const float*)d_in[1];
    const float* tenv  = (const float*)d_in[2];
    const float* ctab  = (const float*)d_in[3];
    const float* w1    = (const float*)d_in[4];
    // d_in[5] = b1 (cancels inside BN)
    const float* g1    = (const float*)d_in[6];
    const float* beta1 = (const float*)d_in[7];
    const float* w2    = (const float*)d_in[8];
    // d_in[9] = b2 (cancels inside BN)
    const float* g2    = (const float*)d_in[10];
    const float* beta2 = (const float*)d_in[11];
    const float* w3    = (const float*)d_in[12];
    const float* b3    = (const float*)d_in[13];
    float* out = (float*)d_out;

    k1_feat<<<NB1, 256>>>(x, tset, tenv, ctab);
    k2_fin1<<<1, 512>>>(w1, g1, beta1);
    k3a_layer1<<<(B_ROWS * 128) / 256, 256>>>();
    dim3 g3(B_ROWS / TM, HID / TN);
    k3b_gemm<<<g3, 256>>>(w2);
    k4_stats<<<RG2, 256>>>();
    k5_fin2<<<2, 256>>>(g2, beta2);
    k6_out<<<2048, 256>>>(w3, b3, out);
}

// round 3
// speedup vs baseline: 1.9011x; 1.9011x over previous
#include <cuda_runtime.h>
#include <cuda_bf16.h>
#include <math.h>
#include <stdint.h>

#define B_ROWS 262144
#define HID 512
#define NB1 512
#define RG2 1024

// ---------------- device scratch ----------------
__device__ __nv_bfloat16 g_Ahi[(size_t)B_ROWS * HID];
__device__ __nv_bfloat16 g_Alo[(size_t)B_ROWS * HID];
__device__ __nv_bfloat16 g_Bhi[HID * HID];   // [n][k] = w2[k][n] hi
__device__ __nv_bfloat16 g_Blo[HID * HID];
__device__ float  g_h2[(size_t)B_ROWS * HID];
__device__ float  g_feat[B_ROWS * 4];
__device__ double g_p1[NB1 * 14];
__device__ float  g_W1eff[4 * HID];
__device__ float  g_meanX[4];
__device__ float  g_shift1[HID];
__device__ float  g_p2s[RG2 * HID];
__device__ float  g_p2q[RG2 * HID];
__device__ float  g_a2[HID];
__device__ float  g_d2[HID];

// ---------------- PTX helpers (all sm_80-level: safe at compute_103) ----------------
__device__ __forceinline__ uint32_t smem_u32(const void* p) {
    uint32_t a;
    asm("{ .reg .u64 t; cvta.to.shared.u64 t, %1; cvt.u32.u64 %0, t; }" : "=r"(a) : "l"(p));
    return a;
}
#define CP_ASYNC16(dst, src) \
    asm volatile("cp.async.cg.shared.global [%0], [%1], 16;" :: "r"(dst), "l"(src) : "memory")
#define CP_COMMIT() asm volatile("cp.async.commit_group;" ::: "memory")
#define CP_WAIT(n)  asm volatile("cp.async.wait_group %0;" :: "n"(n) : "memory")
#define LDSM_X4(r0, r1, r2, r3, addr) \
    asm volatile("ldmatrix.sync.aligned.m8n8.x4.shared.b16 {%0,%1,%2,%3}, [%4];" \
        : "=r"(r0), "=r"(r1), "=r"(r2), "=r"(r3) : "r"(addr))
#define MMA16816(d, a, b0, b1) \
    asm volatile("mma.sync.aligned.m16n8k16.row.col.f32.bf16.bf16.f32 " \
        "{%0,%1,%2,%3},{%4,%5,%6,%7},{%8,%9},{%0,%1,%2,%3};" \
        : "+f"((d)[0]), "+f"((d)[1]), "+f"((d)[2]), "+f"((d)[3]) \
        : "r"((a)[0]), "r"((a)[1]), "r"((a)[2]), "r"((a)[3]), "r"(b0), "r"(b1))

__device__ __forceinline__ float ftanh(float x) {
    x = fminf(fmaxf(x, -9.0f), 9.0f);
    float e = __expf(2.0f * x);
    return __fdividef(e - 1.0f, e + 1.0f);
}

// ---------------- K1: features + (sum, second-moment) partials ----------------
__global__ void k1_feat(const float* __restrict__ x,
                        const float* __restrict__ tset,
                        const float* __restrict__ tenv,
                        const float* __restrict__ ctab)
{
    __shared__ float sxs[9], sys[14], stab[9 * 14];
    int tid = threadIdx.x;
    if (tid < 9)   sxs[tid] = tset[tid];
    if (tid < 14)  sys[tid] = tenv[tid];
    if (tid < 126) stab[tid] = ctab[tid];
    __syncthreads();

    double s0 = 0, s1 = 0, s2 = 0, s3 = 0;
    double m00 = 0, m01 = 0, m02 = 0, m03 = 0, m11 = 0, m12 = 0, m13 = 0,
           m22 = 0, m23 = 0, m33 = 0;

    for (int r = blockIdx.x * blockDim.x + tid; r < B_ROWS; r += gridDim.x * blockDim.x) {
        const float* xr = x + (size_t)r * 15;
        float amb = xr[1], fl = xr[2], fr = xr[3];
        float incar = xr[8], breq = xr[9], cin = xr[10];

        float yq = fminf(fmaxf(amb, sys[0]), sys[13]);
        int j = 0;
        #pragma unroll
        for (int k = 1; k <= 12; k++) j += (sys[k] <= yq);
        float y0 = sys[j], y1 = sys[j + 1];
        float ty = (yq - y0) / (y1 - y0);

        auto interp = [&](float xq) -> float {
            xq = fminf(fmaxf(xq, sxs[0]), sxs[8]);
            int i = 0;
            #pragma unroll
            for (int k = 1; k <= 7; k++) i += (sxs[k] <= xq);
            float x0 = sxs[i], x1 = sxs[i + 1];
            float tx = (xq - x0) / (x1 - x0);
            float f00 = stab[i * 14 + j],       f01 = stab[i * 14 + j + 1];
            float f10 = stab[(i + 1) * 14 + j], f11 = stab[(i + 1) * 14 + j + 1];
            return f00 * (1.f - tx) * (1.f - ty) + f10 * tx * (1.f - ty)
                 + f01 * (1.f - tx) * ty        + f11 * tx * ty;
        };

        float f0 = interp(fl) - incar;
        float f1 = interp(fr) - incar;
        float f2 = amb;
        float f3 = breq - cin;
        *(float4*)&g_feat[(size_t)r * 4] = make_float4(f0, f1, f2, f3);

        s0 += f0; s1 += f1; s2 += f2; s3 += f3;
        m00 += (double)f0 * f0; m01 += (double)f0 * f1; m02 += (double)f0 * f2; m03 += (double)f0 * f3;
        m11 += (double)f1 * f1; m12 += (double)f1 * f2; m13 += (double)f1 * f3;
        m22 += (double)f2 * f2; m23 += (double)f2 * f3; m33 += (double)f3 * f3;
    }

    __shared__ double red[256];
    double vals[14] = {s0, s1, s2, s3, m00, m01, m02, m03, m11, m12, m13, m22, m23, m33};
    for (int q = 0; q < 14; q++) {
        red[tid] = vals[q];
        __syncthreads();
        for (int off = 128; off > 0; off >>= 1) {
            if (tid < off) red[tid] += red[tid + off];
            __syncthreads();
        }
        if (tid == 0) g_p1[blockIdx.x * 14 + q] = red[0];
        __syncthreads();
    }
}

// ---------------- K2: finalize layer-1 BN fold ----------------
__global__ void k2_fin1(const float* __restrict__ w1,
                        const float* __restrict__ g1,
                        const float* __restrict__ beta1)
{
    __shared__ double acc[14];
    __shared__ float C[4][4];
    int tid = threadIdx.x;
    if (tid < 14) {
        double s = 0;
        for (int p = 0; p < NB1; p++) s += g_p1[p * 14 + tid];
        acc[tid] = s;
    }
    __syncthreads();
    if (tid == 0) {
        double inv = 1.0 / (double)B_ROWS;
        double mm[4];
        for (int a = 0; a < 4; a++) { mm[a] = acc[a] * inv; g_meanX[a] = (float)mm[a]; }
        double M[4][4];
        int idx = 4;
        for (int a = 0; a < 4; a++)
            for (int b = a; b < 4; b++) M[a][b] = acc[idx++] * inv;
        for (int a = 0; a < 4; a++)
            for (int b = a; b < 4; b++) {
                double c = M[a][b] - mm[a] * mm[b];
                C[a][b] = (float)c; C[b][a] = (float)c;
            }
    }
    __syncthreads();
    if (tid < HID) {
        float w[4];
        for (int a = 0; a < 4; a++) w[a] = w1[a * HID + tid];
        float var = 0.f;
        for (int a = 0; a < 4; a++)
            for (int b = 0; b < 4; b++) var += w[a] * C[a][b] * w[b];
        float s = g1[tid] * rsqrtf(var + 1e-5f);
        for (int a = 0; a < 4; a++) g_W1eff[a * HID + tid] = w[a] * s;
        g_shift1[tid] = beta1[tid];
    }
}

// ---------------- K2b: split-transpose w2 -> B_hi/B_lo [n][k] bf16 ----------------
__global__ void k2b_bsplit(const float* __restrict__ w2)
{
    int idx = blockIdx.x * 256 + threadIdx.x;
    int n = idx >> 9, k = idx & 511;
    float w = w2[k * HID + n];
    __nv_bfloat16 hi = __float2bfloat16(w);
    float lo = w - __bfloat162float(hi);
    g_Bhi[n * HID + k] = hi;
    g_Blo[n * HID + k] = __float2bfloat16(lo);
}

// ---------------- K3a: t1 = tanh(Xc @ W1eff + beta1), write bf16 hi/lo ----------------
__global__ void k3a_layer1()
{
    int idx = blockIdx.x * blockDim.x + threadIdx.x;
    int r = idx >> 7;
    int jc = (idx & 127) * 4;
    float4 f = *(const float4*)&g_feat[(size_t)r * 4];
    float fc0 = f.x - g_meanX[0], fc1 = f.y - g_meanX[1];
    float fc2 = f.z - g_meanX[2], fc3 = f.w - g_meanX[3];
    __nv_bfloat16 hi[4], lo[4];
    #pragma unroll
    for (int u = 0; u < 4; u++) {
        int j = jc + u;
        float v = fc0 * g_W1eff[0 * HID + j] + fc1 * g_W1eff[1 * HID + j]
                + fc2 * g_W1eff[2 * HID + j] + fc3 * g_W1eff[3 * HID + j]
                + g_shift1[j];
        float t = ftanh(v);
        hi[u] = __float2bfloat16(t);
        lo[u] = __float2bfloat16(t - __bfloat162float(hi[u]));
    }
    size_t base = (size_t)r * HID + jc;
    *(__nv_bfloat162*)(g_Ahi + base)     = *(__nv_bfloat162*)&hi[0];
    *(__nv_bfloat162*)(g_Ahi + base + 2) = *(__nv_bfloat162*)&hi[2];
    *(__nv_bfloat162*)(g_Alo + base)     = *(__nv_bfloat162*)&lo[0];
    *(__nv_bfloat162*)(g_Alo + base + 2) = *(__nv_bfloat162*)&lo[2];
}

// ---------------- K3b: h2 = t1 @ w2 via mma.sync bf16, 3-term split ----------------
// CTA tile 128x128, 8 warps (warp tile 32x64), KSTAGE=32, 2-stage cp.async ring.
#define KSTAGE 32
#define ROWPAD 80                      // 64B data + 16B pad: conflict-free ldmatrix
#define TILEB (128 * ROWPAD)           // 10240 per array
#define OFF_AHI 0
#define OFF_ALO (TILEB)
#define OFF_BHI (2 * TILEB)
#define OFF_BLO (3 * TILEB)
#define STAGEB (4 * TILEB)             // 40960
#define GEMM_SMEM (2 * STAGEB)         // 81920

__global__ void __launch_bounds__(256, 2) k3b_gemm()
{
    extern __shared__ char smem[];
    const uint32_t sb = smem_u32(smem);
    const int tid = threadIdx.x;
    const int wid = tid >> 5, lane = tid & 31;
    const int bn = blockIdx.x, bm = blockIdx.y;
    const size_t arow0 = (size_t)bm * 128;
    const int ncol0 = bn * 128;

    // ---- stage loader ----
    auto load_stage = [&](int s) {
        uint32_t stg = sb + (s & 1) * STAGEB;
        int kk = s * KSTAGE;
        #pragma unroll
        for (int h = 0; h < 2; h++) {
            int idx = tid + h * 256;          // 512 chunks of 16B per array
            int r = idx >> 2, c = idx & 3;
            uint32_t doff = r * ROWPAD + c * 16;
            size_t gA = (arow0 + r) * HID + kk + c * 8;
            size_t gB = (size_t)(ncol0 + r) * HID + kk + c * 8;
            CP_ASYNC16(stg + OFF_AHI + doff, g_Ahi + gA);
            CP_ASYNC16(stg + OFF_ALO + doff, g_Alo + gA);
            CP_ASYNC16(stg + OFF_BHI + doff, g_Bhi + gB);
            CP_ASYNC16(stg + OFF_BLO + doff, g_Blo + gB);
        }
    };

    const int warp_m = wid & 3;        // 4 warps along M
    const int warp_n = wid >> 2;       // 2 warps along N

    float acc[2][8][4];
    #pragma unroll
    for (int i = 0; i < 2; i++)
        #pragma unroll
        for (int j = 0; j < 8; j++)
            #pragma unroll
            for (int q = 0; q < 4; q++) acc[i][j][q] = 0.f;

    // ldmatrix lane->address components (constant over stages)
    const int a_row = warp_m * 32 + (lane & 15);        // + im*16
    const uint32_t a_koff = (lane >> 4) * 16;           // + kstep*32
    const int b_row = warp_n * 64 + (lane & 7) + ((lane >> 4) & 1) * 8;  // + ng*16
    const uint32_t b_koff = ((lane >> 3) & 1) * 16;

    load_stage(0);
    CP_COMMIT();

    for (int s = 0; s < HID / KSTAGE; s++) {
        if (s + 1 < HID / KSTAGE) {
            load_stage(s + 1);
            CP_COMMIT();
            CP_WAIT(1);
        } else {
            CP_WAIT(0);
        }
        __syncthreads();

        uint32_t stg = sb + (s & 1) * STAGEB;
        #pragma unroll
        for (int ks = 0; ks < 2; ks++) {
            uint32_t kb = ks * 32;    // 16 k-elems * 2B
            uint32_t ah[2][4], al[2][4];
            #pragma unroll
            for (int im = 0; im < 2; im++) {
                uint32_t aaddr = stg + (uint32_t)(a_row + im * 16) * ROWPAD + kb + a_koff;
                LDSM_X4(ah[im][0], ah[im][1], ah[im][2], ah[im][3], aaddr + OFF_AHI);
                LDSM_X4(al[im][0], al[im][1], al[im][2], al[im][3], aaddr + OFF_ALO);
            }
            #pragma unroll
            for (int ng = 0; ng < 4; ng++) {
                uint32_t baddr = stg + (uint32_t)(b_row + ng * 16) * ROWPAD + kb + b_koff;
                uint32_t bh[4], bl[4];
                LDSM_X4(bh[0], bh[1], bh[2], bh[3], baddr + OFF_BHI);
                LDSM_X4(bl[0], bl[1], bl[2], bl[3], baddr + OFF_BLO);
                #pragma unroll
                for (int im = 0; im < 2; im++) {
                    #pragma unroll
                    for (int h = 0; h < 2; h++) {
                        MMA16816(acc[im][ng * 2 + h], ah[im], bh[2 * h], bh[2 * h + 1]);
                        MMA16816(acc[im][ng * 2 + h], al[im], bh[2 * h], bh[2 * h + 1]);
                        MMA16816(acc[im][ng * 2 + h], ah[im], bl[2 * h], bl[2 * h + 1]);
                    }
                }
            }
        }
        __syncthreads();
    }

    // ---- epilogue: write 32x64 warp tile to g_h2 ----
    const size_t rowbase = arow0 + warp_m * 32;
    const int colbase = ncol0 + warp_n * 64;
    #pragma unroll
    for (int im = 0; im < 2; im++) {
        #pragma unroll
        for (int half = 0; half < 2; half++) {
            size_t row = rowbase + im * 16 + (lane >> 2) + half * 8;
            float* dst = g_h2 + row * HID + colbase + (lane & 3) * 2;
            #pragma unroll
            for (int ng2 = 0; ng2 < 8; ng2++) {
                float2 v = make_float2(acc[im][ng2][2 * half], acc[im][ng2][2 * half + 1]);
                *(float2*)(dst + ng2 * 8) = v;
            }
        }
    }
}

// ---------------- K4: per-column partial sums / sumsq of h2 ----------------
__global__ void k4_stats()
{
    int bid = blockIdx.x, t = threadIdx.x;
    size_t base = (size_t)bid * 256 * HID;
    float s0 = 0, q0 = 0, s1 = 0, q1 = 0;
    for (int r = 0; r < 256; r++) {
        const float* row = g_h2 + base + (size_t)r * HID;
        float v0 = row[t], v1 = row[t + 256];
        s0 += v0; q0 += v0 * v0;
        s1 += v1; q1 += v1 * v1;
    }
    g_p2s[bid * HID + t] = s0;       g_p2s[bid * HID + t + 256] = s1;
    g_p2q[bid * HID + t] = q0;       g_p2q[bid * HID + t + 256] = q1;
}

// ---------------- K5: finalize layer-2 BN fold ----------------
__global__ void k5_fin2(const float* __restrict__ g2, const float* __restrict__ beta2)
{
    int c = blockIdx.x * blockDim.x + threadIdx.x;
    if (c >= HID) return;
    double s = 0, q = 0;
    for (int p = 0; p < RG2; p++) { s += g_p2s[p * HID + c]; q += g_p2q[p * HID + c]; }
    double mu  = s / (double)B_ROWS;
    double var = q / (double)B_ROWS - mu * mu;
    float a = g2[c] * rsqrtf((float)var + 1e-5f);
    g_a2[c] = a;
    g_d2[c] = beta2[c] - (float)mu * a;
}

// ---------------- K6: out = tanh(a2*h2 + d2) @ w3 + b3 ----------------
__global__ void k6_out(const float* __restrict__ w3, const float* __restrict__ b3,
                       float* __restrict__ out)
{
    __shared__ float sa[HID], sd[HID], sw[HID];
    int t = threadIdx.x;
    for (int q = t; q < HID; q += 256) { sa[q] = g_a2[q]; sd[q] = g_d2[q]; sw[q] = w3[q]; }
    __syncthreads();
    float bias = b3[0];
    int warp = t >> 5, lane = t & 31;
    int gw = blockIdx.x * 8 + warp;
    for (int r = gw; r < B_ROWS; r += 16384) {
        const float* row = g_h2 + (size_t)r * HID;
        float acc = 0.f;
        #pragma unroll
        for (int cc = 0; cc < 16; cc++) {
            int c = cc * 32 + lane;
            acc += ftanh(fmaf(sa[c], row[c], sd[c])) * sw[c];
        }
        #pragma unroll
        for (int off = 16; off; off >>= 1) acc += __shfl_xor_sync(0xffffffffu, acc, off);
        if (lane == 0) out[r] = acc + bias;
    }
}

// ---------------- launch ----------------
extern "C" void kernel_launch(void* const* d_in, const int* in_sizes, int n_in,
                              void* d_out, int out_size)
{
    const float* x     = (const float*)d_in[0];
    const float* tset  = (const float*)d_in[1];
    const float* tenv  = (const float*)d_in[2];
    const float* ctab  = (const float*)d_in[3];
    const float* w1    = (const float*)d_in[4];
    const float* g1    = (const float*)d_in[6];
    const float* beta1 = (const float*)d_in[7];
    const float* w2    = (const float*)d_in[8];
    const float* g2    = (const float*)d_in[10];
    const float* beta2 = (const float*)d_in[11];
    const float* w3    = (const float*)d_in[12];
    const float* b3    = (const float*)d_in[13];
    float* out = (float*)d_out;

    static bool attr_set = false;
    if (!attr_set) {
        cudaFuncSetAttribute(k3b_gemm, cudaFuncAttributeMaxDynamicSharedMemorySize, GEMM_SMEM);
        attr_set = true;
    }

    k1_feat<<<NB1, 256>>>(x, tset, tenv, ctab);
    k2_fin1<<<1, 512>>>(w1, g1, beta1);
    k2b_bsplit<<<HID * HID / 256, 256>>>(w2);
    k3a_layer1<<<(B_ROWS * 128) / 256, 256>>>();
    dim3 g3(4, B_ROWS / 128);
    k3b_gemm<<<g3, 256, GEMM_SMEM>>>();
    k4_stats<<<RG2, 256>>>();
    k5_fin2<<<2, 256>>>(g2, beta2);
    k6_out<<<2048, 256>>>(w3, b3, out);
}

// round 4
// speedup vs baseline: 4.9077x; 2.5815x over previous
#include <cuda_runtime.h>
#include <cuda_fp16.h>
#include <math.h>
#include <stdint.h>

#define B_ROWS 262144
#define HID 512
#define NB1 512
#define NPART 2048         // GEMM bm count = stats partials

// ---------------- device scratch ----------------
__device__ __half g_A[(size_t)B_ROWS * HID];      // t1 fp16
__device__ __half g_B[HID * HID];                 // [n][k] = w2[k][n] fp16
__device__ float  g_h2[(size_t)B_ROWS * HID];
__device__ float  g_feat[B_ROWS * 4];
__device__ double g_p1[NB1 * 14];
__device__ float  g_W1eff[4 * HID];
__device__ float  g_meanX[4];
__device__ float  g_shift1[HID];
__device__ float  g_p2s[(size_t)NPART * HID];     // per-(bm) column partial sums
__device__ float  g_p2q[(size_t)NPART * HID];
__device__ float  g_a2[HID];
__device__ float  g_d2[HID];

// ---------------- PTX helpers (sm_80-level, safe at compute_103) ----------------
__device__ __forceinline__ uint32_t smem_u32(const void* p) {
    uint32_t a;
    asm("{ .reg .u64 t; cvta.to.shared.u64 t, %1; cvt.u32.u64 %0, t; }" : "=r"(a) : "l"(p));
    return a;
}
#define CP_ASYNC16(dst, src) \
    asm volatile("cp.async.cg.shared.global [%0], [%1], 16;" :: "r"(dst), "l"(src) : "memory")
#define CP_COMMIT() asm volatile("cp.async.commit_group;" ::: "memory")
#define CP_WAIT(n)  asm volatile("cp.async.wait_group %0;" :: "n"(n) : "memory")
#define LDSM_X4(r0, r1, r2, r3, addr) \
    asm volatile("ldmatrix.sync.aligned.m8n8.x4.shared.b16 {%0,%1,%2,%3}, [%4];" \
        : "=r"(r0), "=r"(r1), "=r"(r2), "=r"(r3) : "r"(addr))
#define MMA16816F16(d, a, b0, b1) \
    asm volatile("mma.sync.aligned.m16n8k16.row.col.f32.f16.f16.f32 " \
        "{%0,%1,%2,%3},{%4,%5,%6,%7},{%8,%9},{%0,%1,%2,%3};" \
        : "+f"((d)[0]), "+f"((d)[1]), "+f"((d)[2]), "+f"((d)[3]) \
        : "r"((a)[0]), "r"((a)[1]), "r"((a)[2]), "r"((a)[3]), "r"(b0), "r"(b1))

__device__ __forceinline__ float ftanh(float x) {
    x = fminf(fmaxf(x, -9.0f), 9.0f);
    float e = __expf(2.0f * x);
    return __fdividef(e - 1.0f, e + 1.0f);
}

// ---------------- K1: features + (sum, second-moment) partials ----------------
__global__ void k1_feat(const float* __restrict__ x,
                        const float* __restrict__ tset,
                        const float* __restrict__ tenv,
                        const float* __restrict__ ctab)
{
    __shared__ float sxs[9], sys[14], stab[9 * 14];
    int tid = threadIdx.x;
    if (tid < 9)   sxs[tid] = tset[tid];
    if (tid < 14)  sys[tid] = tenv[tid];
    if (tid < 126) stab[tid] = ctab[tid];
    __syncthreads();

    double s0 = 0, s1 = 0, s2 = 0, s3 = 0;
    double m00 = 0, m01 = 0, m02 = 0, m03 = 0, m11 = 0, m12 = 0, m13 = 0,
           m22 = 0, m23 = 0, m33 = 0;

    for (int r = blockIdx.x * blockDim.x + tid; r < B_ROWS; r += gridDim.x * blockDim.x) {
        const float* xr = x + (size_t)r * 15;
        float amb = xr[1], fl = xr[2], fr = xr[3];
        float incar = xr[8], breq = xr[9], cin = xr[10];

        float yq = fminf(fmaxf(amb, sys[0]), sys[13]);
        int j = 0;
        #pragma unroll
        for (int k = 1; k <= 12; k++) j += (sys[k] <= yq);
        float y0 = sys[j], y1 = sys[j + 1];
        float ty = (yq - y0) / (y1 - y0);

        auto interp = [&](float xq) -> float {
            xq = fminf(fmaxf(xq, sxs[0]), sxs[8]);
            int i = 0;
            #pragma unroll
            for (int k = 1; k <= 7; k++) i += (sxs[k] <= xq);
            float x0 = sxs[i], x1 = sxs[i + 1];
            float tx = (xq - x0) / (x1 - x0);
            float f00 = stab[i * 14 + j],       f01 = stab[i * 14 + j + 1];
            float f10 = stab[(i + 1) * 14 + j], f11 = stab[(i + 1) * 14 + j + 1];
            return f00 * (1.f - tx) * (1.f - ty) + f10 * tx * (1.f - ty)
                 + f01 * (1.f - tx) * ty        + f11 * tx * ty;
        };

        float f0 = interp(fl) - incar;
        float f1 = interp(fr) - incar;
        float f2 = amb;
        float f3 = breq - cin;
        *(float4*)&g_feat[(size_t)r * 4] = make_float4(f0, f1, f2, f3);

        s0 += f0; s1 += f1; s2 += f2; s3 += f3;
        m00 += (double)f0 * f0; m01 += (double)f0 * f1; m02 += (double)f0 * f2; m03 += (double)f0 * f3;
        m11 += (double)f1 * f1; m12 += (double)f1 * f2; m13 += (double)f1 * f3;
        m22 += (double)f2 * f2; m23 += (double)f2 * f3; m33 += (double)f3 * f3;
    }

    __shared__ double red[256];
    double vals[14] = {s0, s1, s2, s3, m00, m01, m02, m03, m11, m12, m13, m22, m23, m33};
    for (int q = 0; q < 14; q++) {
        red[tid] = vals[q];
        __syncthreads();
        for (int off = 128; off > 0; off >>= 1) {
            if (tid < off) red[tid] += red[tid + off];
            __syncthreads();
        }
        if (tid == 0) g_p1[blockIdx.x * 14 + q] = red[0];
        __syncthreads();
    }
}

// ---------------- K2: finalize layer-1 BN fold ----------------
__global__ void k2_fin1(const float* __restrict__ w1,
                        const float* __restrict__ g1,
                        const float* __restrict__ beta1)
{
    __shared__ double acc[14];
    __shared__ float C[4][4];
    int tid = threadIdx.x;
    if (tid < 14) {
        double s = 0;
        for (int p = 0; p < NB1; p++) s += g_p1[p * 14 + tid];
        acc[tid] = s;
    }
    __syncthreads();
    if (tid == 0) {
        double inv = 1.0 / (double)B_ROWS;
        double mm[4];
        for (int a = 0; a < 4; a++) { mm[a] = acc[a] * inv; g_meanX[a] = (float)mm[a]; }
        double M[4][4];
        int idx = 4;
        for (int a = 0; a < 4; a++)
            for (int b = a; b < 4; b++) M[a][b] = acc[idx++] * inv;
        for (int a = 0; a < 4; a++)
            for (int b = a; b < 4; b++) {
                double c = M[a][b] - mm[a] * mm[b];
                C[a][b] = (float)c; C[b][a] = (float)c;
            }
    }
    __syncthreads();
    if (tid < HID) {
        float w[4];
        for (int a = 0; a < 4; a++) w[a] = w1[a * HID + tid];
        float var = 0.f;
        for (int a = 0; a < 4; a++)
            for (int b = 0; b < 4; b++) var += w[a] * C[a][b] * w[b];
        float s = g1[tid] * rsqrtf(var + 1e-5f);
        for (int a = 0; a < 4; a++) g_W1eff[a * HID + tid] = w[a] * s;
        g_shift1[tid] = beta1[tid];
    }
}

// ---------------- K2b: transpose w2 -> B [n][k] fp16 ----------------
__global__ void k2b_bsplit(const float* __restrict__ w2)
{
    int idx = blockIdx.x * 256 + threadIdx.x;
    int n = idx >> 9, k = idx & 511;
    g_B[n * HID + k] = __float2half_rn(w2[k * HID + n]);
}

// ---------------- K3a: t1 = tanh(Xc @ W1eff + beta1) -> fp16 ----------------
// 8 rows x 4 cols per thread; weights register-resident (amortized over rows).
__global__ void __launch_bounds__(256) k3a_layer1()
{
    int tid = threadIdx.x;
    int jc = (tid & 127) * 4;
    int r0 = blockIdx.x * 16 + (tid >> 7) * 8;

    float4 w0 = *(const float4*)&g_W1eff[0 * HID + jc];
    float4 w1v = *(const float4*)&g_W1eff[1 * HID + jc];
    float4 w2v = *(const float4*)&g_W1eff[2 * HID + jc];
    float4 w3v = *(const float4*)&g_W1eff[3 * HID + jc];
    float4 sh = *(const float4*)&g_shift1[jc];
    float m0 = g_meanX[0], m1 = g_meanX[1], m2 = g_meanX[2], m3 = g_meanX[3];

    #pragma unroll
    for (int rr = 0; rr < 8; rr++) {
        int r = r0 + rr;
        float4 f = *(const float4*)&g_feat[(size_t)r * 4];
        float a = f.x - m0, b = f.y - m1, c = f.z - m2, d = f.w - m3;
        float v0 = a * w0.x + b * w1v.x + c * w2v.x + d * w3v.x + sh.x;
        float v1 = a * w0.y + b * w1v.y + c * w2v.y + d * w3v.y + sh.y;
        float v2 = a * w0.z + b * w1v.z + c * w2v.z + d * w3v.z + sh.z;
        float v3 = a * w0.w + b * w1v.w + c * w2v.w + d * w3v.w + sh.w;
        __half2 p0 = __floats2half2_rn(ftanh(v0), ftanh(v1));
        __half2 p1 = __floats2half2_rn(ftanh(v2), ftanh(v3));
        uint2 pk = make_uint2(*(uint32_t*)&p0, *(uint32_t*)&p1);
        *(uint2*)(g_A + (size_t)r * HID + jc) = pk;
    }
}

// ---------------- K3b: h2 = t1 @ w2 (fp16 mma.sync) + fused column stats ----------------
// CTA tile 128x128, 8 warps (warp tile 32x64), KSTAGE=64, 2-stage cp.async.
#define KSTAGE 64
#define ROWPAD 144                     // 128B data + 16B pad (conflict-free ldmatrix)
#define OFF_A 0
#define OFF_B (128 * ROWPAD)           // 18432
#define STAGEB (256 * ROWPAD)          // 36864
#define GEMM_SMEM (2 * STAGEB)         // 73728

__global__ void __launch_bounds__(256, 2) k3b_gemm()
{
    extern __shared__ char smem[];
    const uint32_t sb = smem_u32(smem);
    const int tid = threadIdx.x;
    const int wid = tid >> 5, lane = tid & 31;
    const int bn = blockIdx.x, bm = blockIdx.y;
    const size_t arow0 = (size_t)bm * 128;
    const int ncol0 = bn * 128;

    auto load_stage = [&](int s) {
        uint32_t stg = sb + (s & 1) * STAGEB;
        int kk = s * KSTAGE;
        #pragma unroll
        for (int h = 0; h < 8; h++) {
            int idx = tid + h * 256;          // 2048 chunks of 16B
            int r = (idx & 1023) >> 3, c = idx & 7;
            uint32_t doff = (uint32_t)r * ROWPAD + c * 16;
            if (idx < 1024) {
                CP_ASYNC16(stg + OFF_A + doff, g_A + (arow0 + r) * HID + kk + c * 8);
            } else {
                CP_ASYNC16(stg + OFF_B + doff, g_B + (size_t)(ncol0 + r) * HID + kk + c * 8);
            }
        }
    };

    const int warp_m = wid & 3;        // 4 warps along M
    const int warp_n = wid >> 2;       // 2 warps along N

    float acc[2][8][4];
    #pragma unroll
    for (int i = 0; i < 2; i++)
        #pragma unroll
        for (int j = 0; j < 8; j++)
            #pragma unroll
            for (int q = 0; q < 4; q++) acc[i][j][q] = 0.f;

    const int a_row = warp_m * 32 + (lane & 15);
    const uint32_t a_koff = (lane >> 4) * 16;
    const int b_row = warp_n * 64 + (lane & 7) + ((lane >> 4) & 1) * 8;
    const uint32_t b_koff = ((lane >> 3) & 1) * 16;

    load_stage(0);
    CP_COMMIT();

    for (int s = 0; s < HID / KSTAGE; s++) {
        if (s + 1 < HID / KSTAGE) {
            load_stage(s + 1);
            CP_COMMIT();
            CP_WAIT(1);
        } else {
            CP_WAIT(0);
        }
        __syncthreads();

        uint32_t stg = sb + (s & 1) * STAGEB;
        #pragma unroll
        for (int ks = 0; ks < 4; ks++) {
            uint32_t kb = ks * 32;
            uint32_t ah[2][4];
            #pragma unroll
            for (int im = 0; im < 2; im++) {
                uint32_t aaddr = stg + OFF_A + (uint32_t)(a_row + im * 16) * ROWPAD + kb + a_koff;
                LDSM_X4(ah[im][0], ah[im][1], ah[im][2], ah[im][3], aaddr);
            }
            #pragma unroll
            for (int ng = 0; ng < 4; ng++) {
                uint32_t baddr = stg + OFF_B + (uint32_t)(b_row + ng * 16) * ROWPAD + kb + b_koff;
                uint32_t bh[4];
                LDSM_X4(bh[0], bh[1], bh[2], bh[3], baddr);
                #pragma unroll
                for (int im = 0; im < 2; im++) {
                    MMA16816F16(acc[im][ng * 2 + 0], ah[im], bh[0], bh[1]);
                    MMA16816F16(acc[im][ng * 2 + 1], ah[im], bh[2], bh[3]);
                }
            }
        }
        __syncthreads();
    }

    // ---- epilogue 1: write 32x64 warp tile to g_h2 ----
    const size_t rowbase = arow0 + warp_m * 32;
    const int colbase = ncol0 + warp_n * 64;
    #pragma unroll
    for (int im = 0; im < 2; im++) {
        #pragma unroll
        for (int half = 0; half < 2; half++) {
            size_t row = rowbase + im * 16 + (lane >> 2) + half * 8;
            float* dst = g_h2 + row * HID + colbase + (lane & 3) * 2;
            #pragma unroll
            for (int ng2 = 0; ng2 < 8; ng2++) {
                float2 v = make_float2(acc[im][ng2][2 * half], acc[im][ng2][2 * half + 1]);
                *(float2*)(dst + ng2 * 8) = v;
            }
        }
    }

    // ---- epilogue 2: fused column sum/sumsq partials (over this CTA's 128 rows) ----
    float* sst = (float*)smem;                      // [4 warp_m][128 col][2]
    #pragma unroll
    for (int ng2 = 0; ng2 < 8; ng2++) {
        #pragma unroll
        for (int e = 0; e < 2; e++) {
            float s = 0.f, q = 0.f;
            #pragma unroll
            for (int im = 0; im < 2; im++) {
                #pragma unroll
                for (int half = 0; half < 2; half++) {
                    float v = acc[im][ng2][2 * half + e];
                    s += v; q += v * v;
                }
            }
            #pragma unroll
            for (int off = 4; off < 32; off <<= 1) {
                s += __shfl_xor_sync(0xffffffffu, s, off);
                q += __shfl_xor_sync(0xffffffffu, q, off);
            }
            if (lane < 4) {
                int col = warp_n * 64 + ng2 * 8 + lane * 2 + e;
                sst[(warp_m * 128 + col) * 2 + 0] = s;
                sst[(warp_m * 128 + col) * 2 + 1] = q;
            }
        }
    }
    __syncthreads();
    if (tid < 256) {
        int col = tid >> 1, sq = tid & 1;
        float v = sst[(0 * 128 + col) * 2 + sq] + sst[(1 * 128 + col) * 2 + sq]
                + sst[(2 * 128 + col) * 2 + sq] + sst[(3 * 128 + col) * 2 + sq];
        size_t gidx = (size_t)bm * HID + bn * 128 + col;
        if (sq == 0) g_p2s[gidx] = v; else g_p2q[gidx] = v;
    }
}

// ---------------- K5: finalize layer-2 BN fold (one block per column) ----------------
__global__ void k5_fin2(const float* __restrict__ g2, const float* __restrict__ beta2)
{
    int c = blockIdx.x;
    int t = threadIdx.x;
    double s = 0, q = 0;
    for (int p = t; p < NPART; p += 256) {
        s += (double)g_p2s[(size_t)p * HID + c];
        q += (double)g_p2q[(size_t)p * HID + c];
    }
    __shared__ double rs[256], rq[256];
    rs[t] = s; rq[t] = q;
    __syncthreads();
    for (int off = 128; off > 0; off >>= 1) {
        if (t < off) { rs[t] += rs[t + off]; rq[t] += rq[t + off]; }
        __syncthreads();
    }
    if (t == 0) {
        double mu  = rs[0] / (double)B_ROWS;
        double var = rq[0] / (double)B_ROWS - mu * mu;
        float a = g2[c] * rsqrtf((float)var + 1e-5f);
        g_a2[c] = a;
        g_d2[c] = beta2[c] - (float)mu * a;
    }
}

// ---------------- K6: out = tanh(a2*h2 + d2) @ w3 + b3 ----------------
__global__ void k6_out(const float* __restrict__ w3, const float* __restrict__ b3,
                       float* __restrict__ out)
{
    __shared__ float sa[HID], sd[HID], sw[HID];
    int t = threadIdx.x;
    for (int q = t; q < HID; q += 256) { sa[q] = g_a2[q]; sd[q] = g_d2[q]; sw[q] = w3[q]; }
    __syncthreads();
    float bias = b3[0];
    int warp = t >> 5, lane = t & 31;
    int gw = blockIdx.x * 8 + warp;
    for (int r = gw; r < B_ROWS; r += 16384) {
        const float* row = g_h2 + (size_t)r * HID;
        float acc = 0.f;
        #pragma unroll
        for (int cc = 0; cc < 16; cc++) {
            int c = cc * 32 + lane;
            acc += ftanh(fmaf(sa[c], row[c], sd[c])) * sw[c];
        }
        #pragma unroll
        for (int off = 16; off; off >>= 1) acc += __shfl_xor_sync(0xffffffffu, acc, off);
        if (lane == 0) out[r] = acc + bias;
    }
}

// ---------------- launch ----------------
extern "C" void kernel_launch(void* const* d_in, const int* in_sizes, int n_in,
                              void* d_out, int out_size)
{
    const float* x     = (const float*)d_in[0];
    const float* tset  = (const float*)d_in[1];
    const float* tenv  = (const float*)d_in[2];
    const float* ctab  = (const float*)d_in[3];
    const float* w1    = (const float*)d_in[4];
    const float* g1    = (const float*)d_in[6];
    const float* beta1 = (const float*)d_in[7];
    const float* w2    = (const float*)d_in[8];
    const float* g2    = (const float*)d_in[10];
    const float* beta2 = (const float*)d_in[11];
    const float* w3    = (const float*)d_in[12];
    const float* b3    = (const float*)d_in[13];
    float* out = (float*)d_out;

    static bool attr_set = false;
    if (!attr_set) {
        cudaFuncSetAttribute(k3b_gemm, cudaFuncAttributeMaxDynamicSharedMemorySize, GEMM_SMEM);
        attr_set = true;
    }

    k1_feat<<<NB1, 256>>>(x, tset, tenv, ctab);
    k2_fin1<<<1, 512>>>(w1, g1, beta1);
    k2b_bsplit<<<HID * HID / 256, 256>>>(w2);
    k3a_layer1<<<B_ROWS / 16, 256>>>();
    dim3 g3(4, B_ROWS / 128);
    k3b_gemm<<<g3, 256, GEMM_SMEM>>>();
    k5_fin2<<<HID, 256>>>(g2, beta2);
    k6_out<<<2048, 256>>>(w3, b3, out);
}

// round 5
// speedup vs baseline: 5.7605x; 1.1738x over previous
#include <cuda_runtime.h>
#include <cuda_fp16.h>
#include <math.h>
#include <stdint.h>

#define B_ROWS 262144
#define HID 512
#define NB1 512
#define NPART 2048         // GEMM bm count = stats partials

// ---------------- device scratch ----------------
__device__ __half g_A[(size_t)B_ROWS * HID];      // t1 fp16
__device__ __half g_B[HID * HID];                 // [n][k] = w2[k][n] fp16
__device__ __half g_h2h[(size_t)B_ROWS * HID];    // h2 fp16 (256 MB)
__device__ float  g_feat[B_ROWS * 4];
__device__ double g_p1[NB1 * 14];
__device__ float  g_W1eff[4 * HID];
__device__ float  g_meanX[4];
__device__ float  g_shift1[HID];
__device__ float  g_p2s[(size_t)NPART * HID];
__device__ float  g_p2q[(size_t)NPART * HID];
__device__ float  g_a2[HID];
__device__ float  g_d2[HID];

// ---------------- PTX helpers (sm_80-level, safe at compute_103) ----------------
__device__ __forceinline__ uint32_t smem_u32(const void* p) {
    uint32_t a;
    asm("{ .reg .u64 t; cvta.to.shared.u64 t, %1; cvt.u32.u64 %0, t; }" : "=r"(a) : "l"(p));
    return a;
}
#define CP_ASYNC16(dst, src) \
    asm volatile("cp.async.cg.shared.global [%0], [%1], 16;" :: "r"(dst), "l"(src) : "memory")
#define CP_COMMIT() asm volatile("cp.async.commit_group;" ::: "memory")
#define CP_WAIT(n)  asm volatile("cp.async.wait_group %0;" :: "n"(n) : "memory")
#define LDSM_X4(r0, r1, r2, r3, addr) \
    asm volatile("ldmatrix.sync.aligned.m8n8.x4.shared.b16 {%0,%1,%2,%3}, [%4];" \
        : "=r"(r0), "=r"(r1), "=r"(r2), "=r"(r3) : "r"(addr))
#define MMA16816F16(d, a, b0, b1) \
    asm volatile("mma.sync.aligned.m16n8k16.row.col.f32.f16.f16.f32 " \
        "{%0,%1,%2,%3},{%4,%5,%6,%7},{%8,%9},{%0,%1,%2,%3};" \
        : "+f"((d)[0]), "+f"((d)[1]), "+f"((d)[2]), "+f"((d)[3]) \
        : "r"((a)[0]), "r"((a)[1]), "r"((a)[2]), "r"((a)[3]), "r"(b0), "r"(b1))

__device__ __forceinline__ float ftanh(float x) {        // accurate path (k6)
    x = fminf(fmaxf(x, -9.0f), 9.0f);
    float e = __expf(2.0f * x);
    return __fdividef(e - 1.0f, e + 1.0f);
}
__device__ __forceinline__ float htanh(float x) {        // HW approx (k3a: pre-fp16 rounding)
    float y;
    asm("tanh.approx.f32 %0, %1;" : "=f"(y) : "f"(x));
    return y;
}

// ---------------- K1: features + (sum, second-moment) partials ----------------
__global__ void k1_feat(const float* __restrict__ x,
                        const float* __restrict__ tset,
                        const float* __restrict__ tenv,
                        const float* __restrict__ ctab)
{
    __shared__ float sxs[9], sys[14], stab[9 * 14];
    int tid = threadIdx.x;
    if (tid < 9)   sxs[tid] = tset[tid];
    if (tid < 14)  sys[tid] = tenv[tid];
    if (tid < 126) stab[tid] = ctab[tid];
    __syncthreads();

    double s0 = 0, s1 = 0, s2 = 0, s3 = 0;
    double m00 = 0, m01 = 0, m02 = 0, m03 = 0, m11 = 0, m12 = 0, m13 = 0,
           m22 = 0, m23 = 0, m33 = 0;

    for (int r = blockIdx.x * blockDim.x + tid; r < B_ROWS; r += gridDim.x * blockDim.x) {
        const float* xr = x + (size_t)r * 15;
        float amb = xr[1], fl = xr[2], fr = xr[3];
        float incar = xr[8], breq = xr[9], cin = xr[10];

        float yq = fminf(fmaxf(amb, sys[0]), sys[13]);
        int j = 0;
        #pragma unroll
        for (int k = 1; k <= 12; k++) j += (sys[k] <= yq);
        float y0 = sys[j], y1 = sys[j + 1];
        float ty = (yq - y0) / (y1 - y0);

        auto interp = [&](float xq) -> float {
            xq = fminf(fmaxf(xq, sxs[0]), sxs[8]);
            int i = 0;
            #pragma unroll
            for (int k = 1; k <= 7; k++) i += (sxs[k] <= xq);
            float x0 = sxs[i], x1 = sxs[i + 1];
            float tx = (xq - x0) / (x1 - x0);
            float f00 = stab[i * 14 + j],       f01 = stab[i * 14 + j + 1];
            float f10 = stab[(i + 1) * 14 + j], f11 = stab[(i + 1) * 14 + j + 1];
            return f00 * (1.f - tx) * (1.f - ty) + f10 * tx * (1.f - ty)
                 + f01 * (1.f - tx) * ty        + f11 * tx * ty;
        };

        float f0 = interp(fl) - incar;
        float f1 = interp(fr) - incar;
        float f2 = amb;
        float f3 = breq - cin;
        *(float4*)&g_feat[(size_t)r * 4] = make_float4(f0, f1, f2, f3);

        s0 += f0; s1 += f1; s2 += f2; s3 += f3;
        m00 += (double)f0 * f0; m01 += (double)f0 * f1; m02 += (double)f0 * f2; m03 += (double)f0 * f3;
        m11 += (double)f1 * f1; m12 += (double)f1 * f2; m13 += (double)f1 * f3;
        m22 += (double)f2 * f2; m23 += (double)f2 * f3; m33 += (double)f3 * f3;
    }

    __shared__ double red[256];
    double vals[14] = {s0, s1, s2, s3, m00, m01, m02, m03, m11, m12, m13, m22, m23, m33};
    for (int q = 0; q < 14; q++) {
        red[tid] = vals[q];
        __syncthreads();
        for (int off = 128; off > 0; off >>= 1) {
            if (tid < off) red[tid] += red[tid + off];
            __syncthreads();
        }
        if (tid == 0) g_p1[blockIdx.x * 14 + q] = red[0];
        __syncthreads();
    }
}

// ---------------- K2: finalize layer-1 BN fold ----------------
__global__ void k2_fin1(const float* __restrict__ w1,
                        const float* __restrict__ g1,
                        const float* __restrict__ beta1)
{
    __shared__ double acc[14];
    __shared__ float C[4][4];
    int tid = threadIdx.x;
    if (tid < 14) {
        double s = 0;
        for (int p = 0; p < NB1; p++) s += g_p1[p * 14 + tid];
        acc[tid] = s;
    }
    __syncthreads();
    if (tid == 0) {
        double inv = 1.0 / (double)B_ROWS;
        double mm[4];
        for (int a = 0; a < 4; a++) { mm[a] = acc[a] * inv; g_meanX[a] = (float)mm[a]; }
        double M[4][4];
        int idx = 4;
        for (int a = 0; a < 4; a++)
            for (int b = a; b < 4; b++) M[a][b] = acc[idx++] * inv;
        for (int a = 0; a < 4; a++)
            for (int b = a; b < 4; b++) {
                double c = M[a][b] - mm[a] * mm[b];
                C[a][b] = (float)c; C[b][a] = (float)c;
            }
    }
    __syncthreads();
    if (tid < HID) {
        float w[4];
        for (int a = 0; a < 4; a++) w[a] = w1[a * HID + tid];
        float var = 0.f;
        for (int a = 0; a < 4; a++)
            for (int b = 0; b < 4; b++) var += w[a] * C[a][b] * w[b];
        float s = g1[tid] * rsqrtf(var + 1e-5f);
        for (int a = 0; a < 4; a++) g_W1eff[a * HID + tid] = w[a] * s;
        g_shift1[tid] = beta1[tid];
    }
}

// ---------------- K2b: transpose w2 -> B [n][k] fp16 ----------------
__global__ void k2b_bsplit(const float* __restrict__ w2)
{
    int idx = blockIdx.x * 256 + threadIdx.x;
    int n = idx >> 9, k = idx & 511;
    g_B[n * HID + k] = __float2half_rn(w2[k * HID + n]);
}

// ---------------- K3a: t1 = tanh(Xc @ W1eff + beta1) -> fp16 ----------------
__global__ void __launch_bounds__(256) k3a_layer1()
{
    int tid = threadIdx.x;
    int jc = (tid & 127) * 4;
    int r0 = blockIdx.x * 16 + (tid >> 7) * 8;

    float4 w0 = *(const float4*)&g_W1eff[0 * HID + jc];
    float4 w1v = *(const float4*)&g_W1eff[1 * HID + jc];
    float4 w2v = *(const float4*)&g_W1eff[2 * HID + jc];
    float4 w3v = *(const float4*)&g_W1eff[3 * HID + jc];
    float4 sh = *(const float4*)&g_shift1[jc];
    float m0 = g_meanX[0], m1 = g_meanX[1], m2 = g_meanX[2], m3 = g_meanX[3];

    #pragma unroll
    for (int rr = 0; rr < 8; rr++) {
        int r = r0 + rr;
        float4 f = *(const float4*)&g_feat[(size_t)r * 4];
        float a = f.x - m0, b = f.y - m1, c = f.z - m2, d = f.w - m3;
        float v0 = a * w0.x + b * w1v.x + c * w2v.x + d * w3v.x + sh.x;
        float v1 = a * w0.y + b * w1v.y + c * w2v.y + d * w3v.y + sh.y;
        float v2 = a * w0.z + b * w1v.z + c * w2v.z + d * w3v.z + sh.z;
        float v3 = a * w0.w + b * w1v.w + c * w2v.w + d * w3v.w + sh.w;
        __half2 p0 = __floats2half2_rn(htanh(v0), htanh(v1));
        __half2 p1 = __floats2half2_rn(htanh(v2), htanh(v3));
        uint2 pk = make_uint2(*(uint32_t*)&p0, *(uint32_t*)&p1);
        *(uint2*)(g_A + (size_t)r * HID + jc) = pk;
    }
}

// ---------------- K3b: h2 = t1 @ w2 (fp16 mma.sync) + fused column stats ----------------
#define KSTAGE 64
#define ROWPAD 144
#define OFF_A 0
#define OFF_B (128 * ROWPAD)           // 18432
#define STAGEB (256 * ROWPAD)          // 36864
#define GEMM_SMEM (2 * STAGEB)         // 73728
#define RSTRIDE 136                    // staging row stride in halves (272B)
#define SST_OFF 49152                  // stats scratch offset (bytes)

__global__ void __launch_bounds__(256, 2) k3b_gemm()
{
    extern __shared__ char smem[];
    const uint32_t sb = smem_u32(smem);
    const int tid = threadIdx.x;
    const int wid = tid >> 5, lane = tid & 31;
    const int bn = blockIdx.x, bm = blockIdx.y;
    const size_t arow0 = (size_t)bm * 128;
    const int ncol0 = bn * 128;

    auto load_stage = [&](int s) {
        uint32_t stg = sb + (s & 1) * STAGEB;
        int kk = s * KSTAGE;
        #pragma unroll
        for (int h = 0; h < 8; h++) {
            int idx = tid + h * 256;
            int r = (idx & 1023) >> 3, c = idx & 7;
            uint32_t doff = (uint32_t)r * ROWPAD + c * 16;
            if (idx < 1024) {
                CP_ASYNC16(stg + OFF_A + doff, g_A + (arow0 + r) * HID + kk + c * 8);
            } else {
                CP_ASYNC16(stg + OFF_B + doff, g_B + (size_t)(ncol0 + r) * HID + kk + c * 8);
            }
        }
    };

    const int warp_m = wid & 3;
    const int warp_n = wid >> 2;

    float acc[2][8][4];
    #pragma unroll
    for (int i = 0; i < 2; i++)
        #pragma unroll
        for (int j = 0; j < 8; j++)
            #pragma unroll
            for (int q = 0; q < 4; q++) acc[i][j][q] = 0.f;

    const int a_row = warp_m * 32 + (lane & 15);
    const uint32_t a_koff = (lane >> 4) * 16;
    const int b_row = warp_n * 64 + (lane & 7) + ((lane >> 4) & 1) * 8;
    const uint32_t b_koff = ((lane >> 3) & 1) * 16;

    load_stage(0);
    CP_COMMIT();

    for (int s = 0; s < HID / KSTAGE; s++) {
        if (s + 1 < HID / KSTAGE) {
            load_stage(s + 1);
            CP_COMMIT();
            CP_WAIT(1);
        } else {
            CP_WAIT(0);
        }
        __syncthreads();

        uint32_t stg = sb + (s & 1) * STAGEB;
        #pragma unroll
        for (int ks = 0; ks < 4; ks++) {
            uint32_t kb = ks * 32;
            uint32_t ah[2][4];
            #pragma unroll
            for (int im = 0; im < 2; im++) {
                uint32_t aaddr = stg + OFF_A + (uint32_t)(a_row + im * 16) * ROWPAD + kb + a_koff;
                LDSM_X4(ah[im][0], ah[im][1], ah[im][2], ah[im][3], aaddr);
            }
            #pragma unroll
            for (int ng = 0; ng < 4; ng++) {
                uint32_t baddr = stg + OFF_B + (uint32_t)(b_row + ng * 16) * ROWPAD + kb + b_koff;
                uint32_t bh[4];
                LDSM_X4(bh[0], bh[1], bh[2], bh[3], baddr);
                #pragma unroll
                for (int im = 0; im < 2; im++) {
                    MMA16816F16(acc[im][ng * 2 + 0], ah[im], bh[0], bh[1]);
                    MMA16816F16(acc[im][ng * 2 + 1], ah[im], bh[2], bh[3]);
                }
            }
        }
        __syncthreads();
    }

    // ---- epilogue 1: pack fp16 into smem staging (conflict-free) ----
    __half* hst = (__half*)smem;          // 128 rows x RSTRIDE halves
    #pragma unroll
    for (int im = 0; im < 2; im++) {
        #pragma unroll
        for (int half = 0; half < 2; half++) {
            int row = warp_m * 32 + im * 16 + (lane >> 2) + half * 8;
            int colb = warp_n * 64 + (lane & 3) * 2;
            #pragma unroll
            for (int ng2 = 0; ng2 < 8; ng2++) {
                __half2 hv = __floats2half2_rn(acc[im][ng2][2 * half], acc[im][ng2][2 * half + 1]);
                *(__half2*)&hst[row * RSTRIDE + colb + ng2 * 8] = hv;
            }
        }
    }

    // ---- epilogue 2: fused column sum/sumsq partials ----
    float* sst = (float*)(smem + SST_OFF);        // [4 warp_m][128 col][2]
    #pragma unroll
    for (int ng2 = 0; ng2 < 8; ng2++) {
        #pragma unroll
        for (int e = 0; e < 2; e++) {
            float s = 0.f, q = 0.f;
            #pragma unroll
            for (int im = 0; im < 2; im++) {
                #pragma unroll
                for (int half = 0; half < 2; half++) {
                    float v = acc[im][ng2][2 * half + e];
                    s += v; q += v * v;
                }
            }
            #pragma unroll
            for (int off = 4; off < 32; off <<= 1) {
                s += __shfl_xor_sync(0xffffffffu, s, off);
                q += __shfl_xor_sync(0xffffffffu, q, off);
            }
            if (lane < 4) {
                int col = warp_n * 64 + ng2 * 8 + lane * 2 + e;
                sst[(warp_m * 128 + col) * 2 + 0] = s;
                sst[(warp_m * 128 + col) * 2 + 1] = q;
            }
        }
    }
    __syncthreads();

    // ---- epilogue 3: coalesced fp16 stores from staging ----
    #pragma unroll
    for (int it = 0; it < 8; it++) {
        int g = it * 256 + tid;               // 2048 chunks of 16B
        int row = g >> 4, ch = g & 15;
        uint4 v = *(uint4*)&hst[row * RSTRIDE + ch * 8];
        *(uint4*)(g_h2h + (arow0 + row) * HID + ncol0 + ch * 8) = v;
    }

    // ---- epilogue 4: reduce stats across warp_m, write partials ----
    if (tid < 256) {
        int col = tid >> 1, sq = tid & 1;
        float v = sst[(0 * 128 + col) * 2 + sq] + sst[(1 * 128 + col) * 2 + sq]
                + sst[(2 * 128 + col) * 2 + sq] + sst[(3 * 128 + col) * 2 + sq];
        size_t gidx = (size_t)bm * HID + bn * 128 + col;
        if (sq == 0) g_p2s[gidx] = v; else g_p2q[gidx] = v;
    }
}

// ---------------- K5: finalize layer-2 BN fold (one block per column) ----------------
__global__ void k5_fin2(const float* __restrict__ g2, const float* __restrict__ beta2)
{
    int c = blockIdx.x;
    int t = threadIdx.x;
    double s = 0, q = 0;
    for (int p = t; p < NPART; p += 256) {
        s += (double)g_p2s[(size_t)p * HID + c];
        q += (double)g_p2q[(size_t)p * HID + c];
    }
    __shared__ double rs[256], rq[256];
    rs[t] = s; rq[t] = q;
    __syncthreads();
    for (int off = 128; off > 0; off >>= 1) {
        if (t < off) { rs[t] += rs[t + off]; rq[t] += rq[t + off]; }
        __syncthreads();
    }
    if (t == 0) {
        double mu  = rs[0] / (double)B_ROWS;
        double var = rq[0] / (double)B_ROWS - mu * mu;
        float a = g2[c] * rsqrtf((float)var + 1e-5f);
        g_a2[c] = a;
        g_d2[c] = beta2[c] - (float)mu * a;
    }
}

// ---------------- K6: out = tanh(a2*h2 + d2) @ w3 + b3 (register-resident consts) ----------------
__global__ void __launch_bounds__(256) k6_out(const float* __restrict__ w3,
                                              const float* __restrict__ b3,
                                              float* __restrict__ out)
{
    int t = threadIdx.x;
    int warp = t >> 5, lane = t & 31;
    float bias = b3[0];

    // each lane owns the same 16 columns for every row it processes
    float ra[16], rd[16], rw[16];
    #pragma unroll
    for (int p = 0; p < 2; p++) {
        int c0 = p * 256 + lane * 8;
        #pragma unroll
        for (int u = 0; u < 4; u++) {
            ra[p * 8 + u]     = g_a2[c0 + u];     rd[p * 8 + u]     = g_d2[c0 + u];
            rw[p * 8 + u]     = w3[c0 + u];
            ra[p * 8 + 4 + u] = g_a2[c0 + 4 + u]; rd[p * 8 + 4 + u] = g_d2[c0 + 4 + u];
            rw[p * 8 + 4 + u] = w3[c0 + 4 + u];
        }
    }

    int gw = blockIdx.x * 8 + warp;
    for (int r = gw; r < B_ROWS; r += 16384) {
        const __half* row = g_h2h + (size_t)r * HID;
        float acc = 0.f;
        #pragma unroll
        for (int p = 0; p < 2; p++) {
            int c0 = p * 256 + lane * 8;
            uint4 v = *(const uint4*)(row + c0);
            float2 f0 = __half22float2(*(__half2*)&v.x);
            float2 f1 = __half22float2(*(__half2*)&v.y);
            float2 f2 = __half22float2(*(__half2*)&v.z);
            float2 f3 = __half22float2(*(__half2*)&v.w);
            float hv[8] = {f0.x, f0.y, f1.x, f1.y, f2.x, f2.y, f3.x, f3.y};
            #pragma unroll
            for (int u = 0; u < 8; u++) {
                int q = p * 8 + u;
                acc += ftanh(fmaf(ra[q], hv[u], rd[q])) * rw[q];
            }
        }
        #pragma unroll
        for (int off = 16; off; off >>= 1) acc += __shfl_xor_sync(0xffffffffu, acc, off);
        if (lane == 0) out[r] = acc + bias;
    }
}

// ---------------- launch ----------------
extern "C" void kernel_launch(void* const* d_in, const int* in_sizes, int n_in,
                              void* d_out, int out_size)
{
    const float* x     = (const float*)d_in[0];
    const float* tset  = (const float*)d_in[1];
    const float* tenv  = (const float*)d_in[2];
    const float* ctab  = (const float*)d_in[3];
    const float* w1    = (const float*)d_in[4];
    const float* g1    = (const float*)d_in[6];
    const float* beta1 = (const float*)d_in[7];
    const float* w2    = (const float*)d_in[8];
    const float* g2    = (const float*)d_in[10];
    const float* beta2 = (const float*)d_in[11];
    const float* w3    = (const float*)d_in[12];
    const float* b3    = (const float*)d_in[13];
    float* out = (float*)d_out;

    static bool attr_set = false;
    if (!attr_set) {
        cudaFuncSetAttribute(k3b_gemm, cudaFuncAttributeMaxDynamicSharedMemorySize, GEMM_SMEM);
        attr_set = true;
    }

    k1_feat<<<NB1, 256>>>(x, tset, tenv, ctab);
    k2_fin1<<<1, 512>>>(w1, g1, beta1);
    k2b_bsplit<<<HID * HID / 256, 256>>>(w2);
    k3a_layer1<<<B_ROWS / 16, 256>>>();
    dim3 g3(4, B_ROWS / 128);
    k3b_gemm<<<g3, 256, GEMM_SMEM>>>();
    k5_fin2<<<HID, 256>>>(g2, beta2);
    k6_out<<<2048, 256>>>(w3, b3, out);
}